// round 17
// baseline (speedup 1.0000x reference)
#include <cuda_runtime.h>
#include <cuda_bf16.h>
#include <math.h>
#include <stdint.h>

#define Bsz 8192
#define Knod 16
#define Eedg 64
#define FIN 300
#define FOUT 64
#define ALPHA 1.0f
#define BETA 0.6f

static __device__ uint4 g_Wfrag[4864];     // encoder B frags: hi [0,2432), lo [2432,4864)
static __device__ uint4 g_WdF[4864];       // decoder B frags: hi [0,2432), lo [2432,4864)
static __device__ float g_contr[Bsz];
static __device__ float g_part[1024 * 4];

// ---------------- helpers ----------------
__device__ __forceinline__ uint32_t pk_bf2(float x, float y) {
    __nv_bfloat162 t = __floats2bfloat162_rn(x, y);   // x in low 16 bits
    return *(uint32_t*)&t;
}
__device__ __forceinline__ float low_bf(uint32_t h)  { return __uint_as_float(h << 16); }
__device__ __forceinline__ float high_bf(uint32_t h) { return __uint_as_float(h & 0xffff0000u); }

__device__ __forceinline__ void mma16816(float* c, uint32_t a0, uint32_t a1, uint32_t a2, uint32_t a3,
                                         uint32_t b0, uint32_t b1) {
    asm volatile(
        "mma.sync.aligned.m16n8k16.row.col.f32.bf16.bf16.f32 "
        "{%0,%1,%2,%3}, {%4,%5,%6,%7}, {%8,%9}, {%0,%1,%2,%3};"
        : "+f"(c[0]), "+f"(c[1]), "+f"(c[2]), "+f"(c[3])
        : "r"(a0), "r"(a1), "r"(a2), "r"(a3), "r"(b0), "r"(b1));
}
__device__ __forceinline__ float wred(float v) {
    v += __shfl_xor_sync(0xffffffffu, v, 16);
    v += __shfl_xor_sync(0xffffffffu, v, 8);
    v += __shfl_xor_sync(0xffffffffu, v, 4);
    v += __shfl_xor_sync(0xffffffffu, v, 2);
    v += __shfl_xor_sync(0xffffffffu, v, 1);
    return v;
}
__device__ __forceinline__ float bsum256(float v, float* sR) {
    int tid = threadIdx.x;
    sR[tid] = v;
    __syncthreads();
#pragma unroll
    for (int s = 128; s > 0; s >>= 1) {
        if (tid < s) sR[tid] += sR[tid + s];
        __syncthreads();
    }
    float r = sR[0];
    __syncthreads();
    return r;
}

// ===========================================================================
// Kernel 0: precompute W_enc + W_dec fragments (bf16 hi/lo, HMMA B layout)
// ===========================================================================
__global__ void prep_W(const float* __restrict__ W_enc, const float* __restrict__ W_dec) {
    int idx = blockIdx.x * blockDim.x + threadIdx.x;
    if (idx < 4864) {
        int lane = idx & 31, nt = (idx >> 5) & 7, kt = idx >> 8;
        int tig = lane & 3, grp = lane >> 2;
        int n = nt * 8 + grp;
        int k0 = kt * 16 + 2 * tig;
        float e0 = __ldg(&W_enc[k0 * 64 + n]);
        float e1 = __ldg(&W_enc[(k0 + 1) * 64 + n]);
        float e2 = (k0 + 8 < FIN) ? __ldg(&W_enc[(k0 + 8) * 64 + n]) : 0.f;
        float e3 = (k0 + 9 < FIN) ? __ldg(&W_enc[(k0 + 9) * 64 + n]) : 0.f;
        uint32_t b0h = pk_bf2(e0, e1), b1h = pk_bf2(e2, e3);
        uint32_t b0l = pk_bf2(e0 - low_bf(b0h), e1 - high_bf(b0h));
        uint32_t b1l = pk_bf2(e2 - low_bf(b1h), e3 - high_bf(b1h));
        uint32_t* gw = (uint32_t*)g_Wfrag;
        int base = (((kt * 4) + (nt >> 1)) * 32 + lane) * 4 + (nt & 1) * 2;
        gw[base] = b0h;  gw[base + 1] = b1h;
        gw[9728 + base] = b0l;  gw[9728 + base + 1] = b1l;
    } else {
        int i2 = idx - 4864;
        if (i2 >= 4864) return;
        int lane = i2 & 31, kt = (i2 >> 5) & 3, nt = i2 >> 7;
        int tig = lane & 3, grp = lane >> 2;
        int n = nt * 8 + grp;
        int k0 = kt * 16 + 2 * tig;
        float e0 = 0.f, e1 = 0.f, e2 = 0.f, e3 = 0.f;
        if (n < FIN) {
            e0 = __ldg(&W_dec[k0 * FIN + n]);
            e1 = __ldg(&W_dec[(k0 + 1) * FIN + n]);
            e2 = __ldg(&W_dec[(k0 + 8) * FIN + n]);
            e3 = __ldg(&W_dec[(k0 + 9) * FIN + n]);
        }
        uint32_t b0h = pk_bf2(e0, e1), b1h = pk_bf2(e2, e3);
        uint32_t b0l = pk_bf2(e0 - low_bf(b0h), e1 - high_bf(b0h));
        uint32_t b1l = pk_bf2(e2 - low_bf(b1h), e3 - high_bf(b1h));
        uint32_t* gw = (uint32_t*)g_WdF;
        int base = (((nt >> 1) * 4 + kt) * 32 + lane) * 4 + (nt & 1) * 2;
        gw[base] = b0h;  gw[base + 1] = b1h;
        gw[9728 + base] = b0l;  gw[9728 + base + 1] = b1l;
    }
}

// ===========================================================================
// MEGA kernel: per-CTA = 8 graphs. Phase 1: HMMA GEMM (3 samples) -> smem Y.
// Phase 2: per-warp graph pipeline. Phase 3: fused HMMA decoder + error.
// ===========================================================================
// smem layout (floats):
#define SYS   66                            // Y row stride (conflict-free)
#define SSTR  (128 * SYS)                   // per-sample Y: 8448
#define SCR   (3 * SSTR)                    // 25344: per-graph scratch base
#define GSTR2 1728
#define OAGG  0
#define OSRC  1024
#define ODST  1088
#define OWE   1152
#define OA    1216
#define OPOOL 1344
#define OSCAL 1536
#define ODEG  1544
#define OND   1560
#define OV    1600
#define SWB   (SCR + 8 * GSTR2)             // 39168: W_bil 64x65 (reused as sDec)
#define SLT   (SWB + 4160)                  // 43328: 16 floats
#define MEGA_SMEM ((SLT + 16) * 4)          // 173376 B

__global__ void __launch_bounds__(256) mega_kernel(
    const float* __restrict__ fp1, const float* __restrict__ fp2,
    const float* __restrict__ fn,
    const float* __restrict__ w_p1, const float* __restrict__ w_p2,
    const float* __restrict__ w_n,
    const float* __restrict__ b_enc, const float* __restrict__ W_bil,
    const float* __restrict__ b_bil, const float* __restrict__ b_dec,
    const int* __restrict__ sp1, const int* __restrict__ dp1,
    const int* __restrict__ sp2, const int* __restrict__ dp2,
    const int* __restrict__ spn, const int* __restrict__ dpn)
{
    extern __shared__ float sm[];
    float* sWb = sm + SWB;
    float* sLT = sm + SLT;
    const int tid = threadIdx.x, lane = tid & 31, g = tid >> 5;
    const int blk = blockIdx.x;
    const int b = blk * 8 + g;
    const int grp = lane >> 2, tig = lane & 3;

    float* scr = sm + SCR + g * GSTR2;
    int* Gsrc = (int*)(scr + OSRC);
    int* Gdst = (int*)(scr + ODST);
    float* Gwe = scr + OWE;

    // cooperative W_bil load (visible after the pre-disc __syncthreads)
    for (int j = tid; j < 4096; j += 256)
        sWb[(j >> 6) * 65 + (j & 63)] = __ldg(&W_bil[j]);

    const float* feats[3] = { fp1 + (size_t)blk * 128 * FIN,
                              fp2 + (size_t)blk * 128 * FIN,
                              fn  + (size_t)blk * 128 * FIN };

    // ================= Phase 1: per-warp GEMM, Y -> smem =================
#pragma unroll 1
    for (int s = 0; s < 3; s++) {
        const float* Ar0 = feats[s] + (size_t)(g * 16 + grp) * FIN;
        const float* Ar1 = Ar0 + 8 * FIN;

        float acc[8][4];
#pragma unroll
        for (int nt = 0; nt < 8; nt++)
#pragma unroll
            for (int q = 0; q < 4; q++) acc[nt][q] = 0.f;

        float2 v00, v10, v01, v11;
        {
            const int c0 = 2 * tig, c1 = c0 + 8;
            v00 = *(const float2*)(Ar0 + c0);
            v10 = *(const float2*)(Ar1 + c0);
            v01 = *(const float2*)(Ar0 + c1);
            v11 = *(const float2*)(Ar1 + c1);
        }

#pragma unroll 1
        for (int kt = 0; kt < 19; kt++) {
            uint32_t ah0 = pk_bf2(v00.x, v00.y);
            uint32_t ah1 = pk_bf2(v10.x, v10.y);
            uint32_t ah2 = pk_bf2(v01.x, v01.y);
            uint32_t ah3 = pk_bf2(v11.x, v11.y);
            uint32_t al0 = pk_bf2(v00.x - low_bf(ah0), v00.y - high_bf(ah0));
            uint32_t al1 = pk_bf2(v10.x - low_bf(ah1), v10.y - high_bf(ah1));
            uint32_t al2 = pk_bf2(v01.x - low_bf(ah2), v01.y - high_bf(ah2));
            uint32_t al3 = pk_bf2(v11.x - low_bf(ah3), v11.y - high_bf(ah3));

            // B fragments straight from L2 (77KB resident, broadcast)
            uint4 H0 = __ldg(&g_Wfrag[(kt * 4 + 0) * 32 + lane]);
            uint4 H1 = __ldg(&g_Wfrag[(kt * 4 + 1) * 32 + lane]);
            uint4 H2 = __ldg(&g_Wfrag[(kt * 4 + 2) * 32 + lane]);
            uint4 H3 = __ldg(&g_Wfrag[(kt * 4 + 3) * 32 + lane]);
            uint4 L0 = __ldg(&g_Wfrag[2432 + (kt * 4 + 0) * 32 + lane]);
            uint4 L1 = __ldg(&g_Wfrag[2432 + (kt * 4 + 1) * 32 + lane]);
            uint4 L2 = __ldg(&g_Wfrag[2432 + (kt * 4 + 2) * 32 + lane]);
            uint4 L3 = __ldg(&g_Wfrag[2432 + (kt * 4 + 3) * 32 + lane]);

            // prefetch next A k-tile
            float2 t00, t10, t01, t11;
            if (kt < 18) {
                const int c0 = (kt + 1) * 16 + 2 * tig;
                const int c1 = c0 + 8;
                t00 = *(const float2*)(Ar0 + c0);
                t10 = *(const float2*)(Ar1 + c0);
                t01 = (c1 < FIN) ? *(const float2*)(Ar0 + c1) : make_float2(0.f, 0.f);
                t11 = (c1 < FIN) ? *(const float2*)(Ar1 + c1) : make_float2(0.f, 0.f);
            } else {
                t00 = v00; t10 = v10; t01 = v01; t11 = v11;
            }

            mma16816(acc[0], ah0, ah1, ah2, ah3, H0.x, H0.y);
            mma16816(acc[1], ah0, ah1, ah2, ah3, H0.z, H0.w);
            mma16816(acc[0], ah0, ah1, ah2, ah3, L0.x, L0.y);
            mma16816(acc[1], ah0, ah1, ah2, ah3, L0.z, L0.w);
            mma16816(acc[0], al0, al1, al2, al3, H0.x, H0.y);
            mma16816(acc[1], al0, al1, al2, al3, H0.z, H0.w);

            mma16816(acc[2], ah0, ah1, ah2, ah3, H1.x, H1.y);
            mma16816(acc[3], ah0, ah1, ah2, ah3, H1.z, H1.w);
            mma16816(acc[2], ah0, ah1, ah2, ah3, L1.x, L1.y);
            mma16816(acc[3], ah0, ah1, ah2, ah3, L1.z, L1.w);
            mma16816(acc[2], al0, al1, al2, al3, H1.x, H1.y);
            mma16816(acc[3], al0, al1, al2, al3, H1.z, H1.w);

            mma16816(acc[4], ah0, ah1, ah2, ah3, H2.x, H2.y);
            mma16816(acc[5], ah0, ah1, ah2, ah3, H2.z, H2.w);
            mma16816(acc[4], ah0, ah1, ah2, ah3, L2.x, L2.y);
            mma16816(acc[5], ah0, ah1, ah2, ah3, L2.z, L2.w);
            mma16816(acc[4], al0, al1, al2, al3, H2.x, H2.y);
            mma16816(acc[5], al0, al1, al2, al3, H2.z, H2.w);

            mma16816(acc[6], ah0, ah1, ah2, ah3, H3.x, H3.y);
            mma16816(acc[7], ah0, ah1, ah2, ah3, H3.z, H3.w);
            mma16816(acc[6], ah0, ah1, ah2, ah3, L3.x, L3.y);
            mma16816(acc[7], ah0, ah1, ah2, ah3, L3.z, L3.w);
            mma16816(acc[6], al0, al1, al2, al3, H3.x, H3.y);
            mma16816(acc[7], al0, al1, al2, al3, H3.z, H3.w);

            v00 = t00; v10 = t10; v01 = t01; v11 = t11;
        }

        // write Y tile to smem (stride 66: rows conflict-free)
        float* Ys = sm + s * SSTR;
#pragma unroll
        for (int nt = 0; nt < 8; nt++) {
            int col = nt * 8 + 2 * tig;
            *(float2*)&Ys[(g * 16 + grp) * SYS + col]     = make_float2(acc[nt][0], acc[nt][1]);
            *(float2*)&Ys[(g * 16 + grp + 8) * SYS + col] = make_float2(acc[nt][2], acc[nt][3]);
        }
    }
    __syncwarp();

    // ================= Phase 2: per-warp graph pipeline =================
    const float2 be = *(const float2*)&b_enc[2 * lane];
    const int* srcs[3] = { sp1 + (long)b * Eedg, sp2 + (long)b * Eedg, spn + (long)b * Eedg };
    const int* dsts[3] = { dp1 + (long)b * Eedg, dp2 + (long)b * Eedg, dpn + (long)b * Eedg };
    const float* wgts[3] = { w_p1 + (long)b * Eedg, w_p2 + (long)b * Eedg, w_n + (long)b * Eedg };

#pragma unroll 1
    for (int s = 0; s < 3; s++) {
        const float* Ys = sm + s * SSTR + (g * 16) * SYS;   // this graph's 16 Y rows
        Gsrc[lane] = __ldg(&srcs[s][lane]);  Gsrc[lane + 32] = __ldg(&srcs[s][lane + 32]);
        Gdst[lane] = __ldg(&dsts[s][lane]);  Gdst[lane + 32] = __ldg(&dsts[s][lane + 32]);
        Gwe[lane]  = __ldg(&wgts[s][lane]);  Gwe[lane + 32]  = __ldg(&wgts[s][lane + 32]);
#pragma unroll
        for (int k = 0; k < Knod; k++)
            *(float2*)&scr[OAGG + k * 64 + 2 * lane] = make_float2(0.f, 0.f);
        __syncwarp();

        // SpMM (x row 0 is zero in encoder -> skip src==0)
        for (int e = 0; e < Eedg; e++) {
            int se = Gsrc[e];
            if (se != 0) {
                int de = Gdst[e]; float w = Gwe[e];
                float2 y = *(const float2*)&Ys[se * SYS + 2 * lane];
                float2* ap = (float2*)&scr[OAGG + de * 64 + 2 * lane];
                float2 a = *ap;
                a.x = fmaf(w, y.x, a.x); a.y = fmaf(w, y.y, a.y);
                *ap = a;
            }
        }

        float px = 0.f, py = 0.f;
        if (s < 2) {
            float2 h2[Knod];
            float ssq[Knod];
#pragma unroll
            for (int k = 0; k < Knod; k++) {
                float2 v = *(const float2*)&scr[OAGG + k * 64 + 2 * lane];
                v.x = fmaxf(v.x + be.x, 0.f); v.y = fmaxf(v.y + be.y, 0.f);
                px += v.x; py += v.y;
                h2[k] = v;
                ssq[k] = v.x * v.x + v.y * v.y;
            }
#pragma unroll
            for (int st = 16; st > 0; st >>= 1)
#pragma unroll
                for (int k = 0; k < Knod; k++)
                    ssq[k] += __shfl_xor_sync(0xffffffffu, ssq[k], st);
#pragma unroll
            for (int k = 0; k < Knod; k++) {
                float inv = 1.f / fmaxf(sqrtf(ssq[k]), 1e-12f);
                float2 v = h2[k];
                v.x *= inv; v.y *= inv;
                *(float2*)&scr[OAGG + k * 64 + 2 * lane] = v;
            }
        } else {
#pragma unroll
            for (int k = 0; k < Knod; k++) {
                float2 v = *(const float2*)&scr[OAGG + k * 64 + 2 * lane];
                px += fmaxf(v.x + be.x, 0.f);
                py += fmaxf(v.y + be.y, 0.f);
            }
        }
        px *= (1.f / 16.f); py *= (1.f / 16.f);
        float pn = wred(px * px + py * py);
        float pinv = 1.f / fmaxf(sqrtf(pn), 1e-12f);
        scr[OPOOL + s * 64 + 2 * lane]     = px * pinv;
        scr[OPOOL + s * 64 + 2 * lane + 1] = py * pinv;

        if (s < 2) {
            float2 av = *(const float2*)&Ys[2 * lane];          // anchor row (node 0)
            av.x = fmaxf(av.x + be.x, 0.f); av.y = fmaxf(av.y + be.y, 0.f);
            float an = wred(av.x * av.x + av.y * av.y);
            float ainv = 1.f / fmaxf(sqrtf(an), 1e-12f);
            scr[OA + s * 64 + 2 * lane]     = av.x * ainv;
            scr[OA + s * 64 + 2 * lane + 1] = av.y * ainv;

            {
                const int target = lane & 15;
                const int* arr = (lane < 16) ? Gsrc : Gdst;
                int c = 0;
                for (int e = 0; e < Eedg; e++) c += (arr[e] == target);
                if (lane < 16) scr[ODEG + lane] = (float)c;
                if (lane == 16) scr[OND + s] = rsqrtf(fmaxf((float)c, 1.f));
            }
            __syncwarp();

            float vx = 0.f, vy = 0.f;
            for (int e = 0; e < Eedg; e++) {
                if (Gdst[e] == 0) {
                    int se = Gsrc[e];
                    float rs = rsqrtf(fmaxf(scr[ODEG + se], 1.f)) * Gwe[e];
                    float2 h2v = *(const float2*)&scr[OAGG + se * 64 + 2 * lane];
                    vx = fmaf(rs, h2v.x, vx);
                    vy = fmaf(rs, h2v.y, vy);
                }
            }
            *(float2*)&scr[OV + s * 64 + 2 * lane] = make_float2(vx, vy);
        }
        __syncwarp();
    }

    // discriminators (needs sWb -> CTA sync)
    __syncthreads();
    {
        const float bb = __ldg(b_bil);
        for (int t = 0; t < 2; t++) {
            float u0 = 0.f, u1 = 0.f;
            const float* wr0 = sWb + lane * 65;
            const float* wr1 = sWb + (lane + 32) * 65;
#pragma unroll 8
            for (int k = 0; k < 64; k++) {
                float ak = scr[OA + t * 64 + k];
                u0 = fmaf(wr0[k], ak, u0);
                u1 = fmaf(wr1[k], ak, u1);
            }
            float dp = wred(scr[OPOOL + t * 64 + lane] * u0 + scr[OPOOL + t * 64 + lane + 32] * u1);
            float dn = wred(scr[OPOOL + 128 + lane] * u0 + scr[OPOOL + 128 + lane + 32] * u1);
            if (lane == 0) {
                scr[OSCAL + t]     = 1.f / (1.f + expf(-(dp + bb)));
                scr[OSCAL + 2 + t] = 1.f / (1.f + expf(-(dn + bb)));
            }
        }
    }
    __syncwarp();

    if (lane == 0) {
        float ps1 = scr[OSCAL + 0], ps2 = scr[OSCAL + 1];
        float ns1 = scr[OSCAL + 2], ns2 = scr[OSCAL + 3];
        sLT[g]     = logf(ps1) + logf(1.f - ns1);
        sLT[8 + g] = logf(ps2) + logf(1.f - ns2);
        g_contr[b] = (ns1 - ps1 + 1.f) * 0.5f + (ns2 - ps2 + 1.f) * 0.5f;
    }

    // ================= Phase 3: fused HMMA decoder + error =================
    __syncthreads();   // V, nd, sLT visible; sWb dead -> reuse as sDec
    float* sDec = sWb; // [4][16][3]

    if (g < 4) {
        uint32_t ah[4][4], al[4][4];
#pragma unroll
        for (int kt = 0; kt < 4; kt++) {
            const int k0 = kt * 16 + 2 * tig;
            const float* V0 = sm + SCR + (grp >> 1) * GSTR2 + OV + (grp & 1) * 64;
            const float* V1 = sm + SCR + ((grp >> 1) + 4) * GSTR2 + OV + (grp & 1) * 64;
            float2 x00 = *(const float2*)(V0 + k0);
            float2 x10 = *(const float2*)(V1 + k0);
            float2 x01 = *(const float2*)(V0 + k0 + 8);
            float2 x11 = *(const float2*)(V1 + k0 + 8);
            ah[kt][0] = pk_bf2(x00.x, x00.y);
            ah[kt][1] = pk_bf2(x10.x, x10.y);
            ah[kt][2] = pk_bf2(x01.x, x01.y);
            ah[kt][3] = pk_bf2(x11.x, x11.y);
            al[kt][0] = pk_bf2(x00.x - low_bf(ah[kt][0]), x00.y - high_bf(ah[kt][0]));
            al[kt][1] = pk_bf2(x10.x - low_bf(ah[kt][1]), x10.y - high_bf(ah[kt][1]));
            al[kt][2] = pk_bf2(x01.x - low_bf(ah[kt][2]), x01.y - high_bf(ah[kt][2]));
            al[kt][3] = pk_bf2(x11.x - low_bf(ah[kt][3]), x11.y - high_bf(ah[kt][3]));
        }
        const float nd0 = sm[SCR + (grp >> 1) * GSTR2 + OND + (grp & 1)];
        const float nd1 = sm[SCR + ((grp >> 1) + 4) * GSTR2 + OND + (grp & 1)];
        const float* ori0 = ((grp & 1) ? fp2 : fp1) +
            (size_t)(blk * 8 + (grp >> 1)) * (Knod * FIN);
        const float* ori1 = ((grp & 1) ? fp2 : fp1) +
            (size_t)(blk * 8 + (grp >> 1) + 4) * (Knod * FIN);

        float shh0 = 0.f, sho0 = 0.f, soo0 = 0.f;
        float shh1 = 0.f, sho1 = 0.f, soo1 = 0.f;

#pragma unroll 1
        for (int ntp = g; ntp < 19; ntp += 4) {
            float acc0[4] = {0.f, 0.f, 0.f, 0.f};
            float acc1[4] = {0.f, 0.f, 0.f, 0.f};
#pragma unroll
            for (int kt = 0; kt < 4; kt++) {
                uint4 H = __ldg(&g_WdF[(ntp * 4 + kt) * 32 + lane]);
                uint4 L = __ldg(&g_WdF[2432 + (ntp * 4 + kt) * 32 + lane]);
                mma16816(acc0, ah[kt][0], ah[kt][1], ah[kt][2], ah[kt][3], H.x, H.y);
                mma16816(acc1, ah[kt][0], ah[kt][1], ah[kt][2], ah[kt][3], H.z, H.w);
                mma16816(acc0, ah[kt][0], ah[kt][1], ah[kt][2], ah[kt][3], L.x, L.y);
                mma16816(acc1, ah[kt][0], ah[kt][1], ah[kt][2], ah[kt][3], L.z, L.w);
                mma16816(acc0, al[kt][0], al[kt][1], al[kt][2], al[kt][3], H.x, H.y);
                mma16816(acc1, al[kt][0], al[kt][1], al[kt][2], al[kt][3], H.z, H.w);
            }
#pragma unroll
            for (int half = 0; half < 2; half++) {
                const float* accP = half ? acc1 : acc0;
                const int col = ntp * 16 + half * 8 + 2 * tig;
                if (col < FIN) {
                    float2 bd = *(const float2*)&b_dec[col];
                    float h00 = fmaxf(accP[0] * nd0 + bd.x, 0.f);
                    float h01 = fmaxf(accP[1] * nd0 + bd.y, 0.f);
                    float h10 = fmaxf(accP[2] * nd1 + bd.x, 0.f);
                    float h11 = fmaxf(accP[3] * nd1 + bd.y, 0.f);
                    float2 o0 = *(const float2*)(ori0 + col);
                    float2 o1 = *(const float2*)(ori1 + col);
                    shh0 += h00 * h00 + h01 * h01;
                    sho0 += h00 * o0.x + h01 * o0.y;
                    soo0 += o0.x * o0.x + o0.y * o0.y;
                    shh1 += h10 * h10 + h11 * h11;
                    sho1 += h10 * o1.x + h11 * o1.y;
                    soo1 += o1.x * o1.x + o1.y * o1.y;
                }
            }
        }

#pragma unroll
        for (int st = 1; st < 4; st <<= 1) {
            shh0 += __shfl_xor_sync(0xffffffffu, shh0, st);
            sho0 += __shfl_xor_sync(0xffffffffu, sho0, st);
            soo0 += __shfl_xor_sync(0xffffffffu, soo0, st);
            shh1 += __shfl_xor_sync(0xffffffffu, shh1, st);
            sho1 += __shfl_xor_sync(0xffffffffu, sho1, st);
            soo1 += __shfl_xor_sync(0xffffffffu, soo1, st);
        }
        if (tig == 0) {
            sDec[(g * 16 + grp) * 3 + 0] = shh0;
            sDec[(g * 16 + grp) * 3 + 1] = sho0;
            sDec[(g * 16 + grp) * 3 + 2] = soo0;
            sDec[(g * 16 + grp + 8) * 3 + 0] = shh1;
            sDec[(g * 16 + grp + 8) * 3 + 1] = sho1;
            sDec[(g * 16 + grp + 8) * 3 + 2] = soo1;
        }
    }
    __syncthreads();

    if (g == 0) {
        float E0c = 0.f, E1c = 0.f, L1c = 0.f, L2c = 0.f;
        if (lane < 16) {
            const int r = lane;
            float shh = sDec[r * 3] + sDec[(16 + r) * 3] + sDec[(32 + r) * 3] + sDec[(48 + r) * 3];
            float sho = sDec[r * 3 + 1] + sDec[(16 + r) * 3 + 1] + sDec[(32 + r) * 3 + 1] + sDec[(48 + r) * 3 + 1];
            float soo = sDec[r * 3 + 2] + sDec[(16 + r) * 3 + 2] + sDec[(32 + r) * 3 + 2] + sDec[(48 + r) * 3 + 2];
            float inv = 1.f / fmaxf(sqrtf(shh), 1e-12f);
            float e = shh * inv * inv - 2.f * inv * sho + soo;
            if (r & 1) E1c = e; else E0c = e;
            if (lane < 8) L1c = sLT[lane];
            else L2c = sLT[lane];
        }
#pragma unroll
        for (int st = 1; st < 32; st <<= 1) {
            E0c += __shfl_xor_sync(0xffffffffu, E0c, st);
            E1c += __shfl_xor_sync(0xffffffffu, E1c, st);
            L1c += __shfl_xor_sync(0xffffffffu, L1c, st);
            L2c += __shfl_xor_sync(0xffffffffu, L2c, st);
        }
        if (lane == 0) {
            g_part[blk * 4 + 0] = E0c;
            g_part[blk * 4 + 1] = E1c;
            g_part[blk * 4 + 2] = L1c;
            g_part[blk * 4 + 3] = L2c;
        }
    }
}

// ===========================================================================
// Kernel 2: fused finalize + scores. 32 CTAs x 256; reduce 1024x4 partials.
// ===========================================================================
__global__ void __launch_bounds__(256) fin_scores(float* out) {
    __shared__ float sR[256];
    const int tid = threadIdx.x;
    float a = 0.f, c = 0.f, m1 = 0.f, m2 = 0.f;
#pragma unroll
    for (int j = 0; j < 4; j++) {
        int p = tid + 256 * j;
        a  += g_part[p * 4 + 0];
        c  += g_part[p * 4 + 1];
        m1 += g_part[p * 4 + 2];
        m2 += g_part[p * 4 + 3];
    }
    float Ssq1 = bsum256(a, sR);
    float Ssq2 = bsum256(c, sR);
    float M1 = bsum256(m1, sR);
    float M2 = bsum256(m2, sR);

    if (blockIdx.x == 0 && tid == 0) {
        float L_con = -(M1 / (float)Bsz + M2 / (float)Bsz) * 0.25f;
        float L_gen = (Ssq1 + Ssq2) / (2.f * (float)Bsz * (float)FIN);
        out[0] = ALPHA * L_con + BETA * L_gen;
    }
    float gen = (sqrtf(Ssq1) + sqrtf(Ssq2)) / (2.f * sqrtf((float)FIN));
    int i = blockIdx.x * 256 + tid;
    out[1 + i] = ALPHA * g_contr[i] + BETA * gen;
}

// ===========================================================================
extern "C" void kernel_launch(void* const* d_in, const int* in_sizes, int n_in,
                              void* d_out, int out_size) {
    const float* feat_p1 = (const float*)d_in[0];
    const float* feat_p2 = (const float*)d_in[1];
    const float* feat_n  = (const float*)d_in[2];
    const float* w_p1    = (const float*)d_in[3];
    const float* w_p2    = (const float*)d_in[4];
    const float* w_n     = (const float*)d_in[5];
    const float* W_enc   = (const float*)d_in[6];
    const float* b_enc   = (const float*)d_in[7];
    const float* W_dec   = (const float*)d_in[8];
    const float* b_dec   = (const float*)d_in[9];
    const float* W_bil   = (const float*)d_in[10];
    const float* b_bil   = (const float*)d_in[11];
    const int* src_p1 = (const int*)d_in[12];
    const int* dst_p1 = (const int*)d_in[13];
    const int* src_p2 = (const int*)d_in[14];
    const int* dst_p2 = (const int*)d_in[15];
    const int* src_n  = (const int*)d_in[16];
    const int* dst_n  = (const int*)d_in[17];
    float* out = (float*)d_out;

    cudaFuncSetAttribute(mega_kernel, cudaFuncAttributeMaxDynamicSharedMemorySize, MEGA_SMEM);

    prep_W<<<38, 256>>>(W_enc, W_dec);

    mega_kernel<<<1024, 256, MEGA_SMEM>>>(
        feat_p1, feat_p2, feat_n, w_p1, w_p2, w_n,
        b_enc, W_bil, b_bil, b_dec,
        src_p1, dst_p1, src_p2, dst_p2, src_n, dst_n);

    fin_scores<<<32, 256>>>(out);
}